// round 14
// baseline (speedup 1.0000x reference)
#include <cuda_runtime.h>
#include <cuda_fp16.h>
#include <math.h>
#include <stdint.h>

// FourierAttention R14: fused scores with 3-buffer rotation + double Apar ->
// ONE barrier per iteration (transform + staging + LDG all overlap main MMA).
// B=4, L=8192, H=16, D=64, Ls=64, M=128.

#define BDIM 4
#define LDIM 8192
#define HDIM 16
#define DDIM 64
#define LSEG 64
#define MSEG 128
#define BH   64
#define KDIM 4096
#define KCH  2
#define LPB  8
#define ROWSTRIDE 1024
#define SEGSTRIDE 65536
#define BSTRIDE (LDIM*ROWSTRIDE)

// Scratch (device globals: allocation-free, graph-capture safe)
__device__ float g_Cpart[(size_t)KCH * BH * MSEG * 256]; // score partials
__device__ __half g_Ah[(size_t)BH * MSEG * MSEG];        // softmax result (fp16)

__device__ __forceinline__ void mma_f16(float* d, const unsigned* a,
                                        unsigned b0, unsigned b1) {
    asm volatile(
        "mma.sync.aligned.m16n8k16.row.col.f32.f16.f16.f32 "
        "{%0,%1,%2,%3},{%4,%5,%6,%7},{%8,%9},{%0,%1,%2,%3};"
        : "+f"(d[0]), "+f"(d[1]), "+f"(d[2]), "+f"(d[3])
        : "r"(a[0]), "r"(a[1]), "r"(a[2]), "r"(a[3]), "r"(b0), "r"(b1));
}

__device__ __forceinline__ unsigned h2u(float a, float b) {
    __half2 h = __floats2half2_rn(a, b);
    return *(unsigned*)&h;
}

__device__ __forceinline__ uint32_t smem_u32(const void* p) {
    uint32_t a;
    asm("{ .reg .u64 t; cvta.to.shared.u64 t, %1; cvt.u32.u64 %0, t; }" : "=r"(a) : "l"(p));
    return a;
}

__device__ __forceinline__ void ldsm_x4(unsigned* r, uint32_t addr) {
    asm volatile("ldmatrix.sync.aligned.m8n8.x4.shared.b16 {%0,%1,%2,%3}, [%4];"
        : "=r"(r[0]), "=r"(r[1]), "=r"(r[2]), "=r"(r[3]) : "r"(addr));
}

// smem (halves): 3 buffers of [As 128x72 | Bs 256x72], 2 Apar copies, taps
#define AS_L 0
#define BS_L (128 * 72)                 // buffer-local
#define BUFH ((128 + 256) * 72)         // 27648 halves per buffer
#define AP_H (3 * BUFH)                 // 82944: Apar[2 copies][2 par][128][40]
#define APC  (2 * 128 * 40)             // 10240 halves per Apar copy
#define TP_H (AP_H + 2 * APC)           // 103424: taps[2][32][40]
#define TOT_H (TP_H + 2 * 32 * 40)      // 105984 halves
#define FS_SMEM (TOT_H * 2)             // 211968 bytes

__global__ __launch_bounds__(512, 1) void scores_fused4(const float* __restrict__ q,
                                                        const float* __restrict__ kin) {
    extern __shared__ __half sh[];

    int kc = blockIdx.x;
    int bh = blockIdx.y;
    int b  = bh >> 4, h = bh & 15;
    int tid  = threadIdx.x;
    int lane = tid & 31;
    int w    = tid >> 5;
    int g = lane >> 2, t4 = lane & 3;
    int m0 = (w >> 2) * 32;
    int j0 = (w & 3) * 64;

    // taps[which][dd][t]
#pragma unroll
    for (int i = tid; i < 2048; i += 512) {
        int which = i >> 10, dd = (i >> 5) & 31, tt = i & 31;
        int delta = which ? (2 * dd + 1 - 2 * tt) : (2 * dd - 2 * tt - 1);
        float x = (float)delta * (1.0f / 64.0f);
        sh[TP_H + which * 1280 + dd * 40 + tt] =
            __float2half(-(cospif(x) / sinpif(x)) * (1.0f / 64.0f));
    }

    float dacc[2][8][4];
#pragma unroll
    for (int mi = 0; mi < 2; mi++)
#pragma unroll
        for (int nj = 0; nj < 8; nj++)
#pragma unroll
            for (int r = 0; r < 4; r++) dacc[mi][nj][r] = 0.0f;

    const float* qb = q   + (size_t)b * BSTRIDE + h * DDIM;
    const float* kb = kin + (size_t)b * BSTRIDE + h * DDIM;

    // staging indices: 4 threads per row
    int n   = tid >> 2;
    int q16 = (tid & 3) * 16;
    int q8  = (tid & 3) * 8;

    uint32_t sb = smem_u32(sh);
    // main-MMA ldsm byte offsets (buffer-local)
    uint32_t offA[2], offB[4];
#pragma unroll
    for (int mi = 0; mi < 2; mi++) {
        int row = m0 + mi * 16 + (lane & 7) + ((lane >> 3) & 1) * 8;
        int col = ((lane >> 4) & 1) * 8;
        offA[mi] = (uint32_t)(AS_L + row * 72 + col) * 2;
    }
#pragma unroll
    for (int njp = 0; njp < 4; njp++) {
        int row = j0 + njp * 16 + (lane & 7) + ((lane >> 4) & 1) * 8;
        int col = ((lane >> 3) & 1) * 8;
        offB[njp] = (uint32_t)(BS_L + row * 72 + col) * 2;
    }
    // transform: warp w handles parity P over 16 n-rows
    int P    = w & 1;
    int nblk = (w >> 1) * 16;
    uint32_t offTA0, offTB;
    {
        int arow = nblk + (lane & 7) + ((lane >> 3) & 1) * 8;
        int acol = ((lane >> 4) & 1) * 8;
        offTA0 = sb + (uint32_t)(AP_H + (1 - P) * 5120 + arow * 40 + acol) * 2;
        int brow = (lane & 7) + ((lane >> 4) & 1) * 8;
        int bcol = ((lane >> 3) & 1) * 8;
        offTB = sb + (uint32_t)(TP_H + P * 1280 + brow * 40 + bcol) * 2;
    }

    int l0 = kc * 32;
    float4 qv[4], kv[4];

#define LDG_IT(LIDX)                                                           \
    {                                                                          \
        const float* sq_ = qb + (size_t)(n * LSEG + (LIDX)) * ROWSTRIDE + q16; \
        const float* sk_ = kb + (size_t)(n * LSEG + (LIDX)) * ROWSTRIDE + q16; \
        _Pragma("unroll")                                                      \
        for (int i_ = 0; i_ < 4; i_++) {                                       \
            qv[i_] = *(const float4*)(sq_ + 4 * i_);                           \
            kv[i_] = *(const float4*)(sk_ + 4 * i_);                           \
        }                                                                      \
    }

#define STAGE(BUF, CP)                                                         \
    {                                                                          \
        __half* bufp = sh + (BUF) * BUFH;                                      \
        __half* app  = sh + AP_H + (CP) * APC;                                 \
        uint4 ua_, ub_;                                                        \
        ua_.x = h2u(qv[0].x, qv[0].y); ua_.y = h2u(qv[0].z, qv[0].w);          \
        ua_.z = h2u(qv[1].x, qv[1].y); ua_.w = h2u(qv[1].z, qv[1].w);          \
        ub_.x = h2u(qv[2].x, qv[2].y); ub_.y = h2u(qv[2].z, qv[2].w);          \
        ub_.z = h2u(qv[3].x, qv[3].y); ub_.w = h2u(qv[3].z, qv[3].w);          \
        *(uint4*)&bufp[AS_L + n * 72 + q16]     = ua_;                         \
        *(uint4*)&bufp[AS_L + n * 72 + q16 + 8] = ub_;                         \
        float e0_=kv[0].x, e1_=kv[0].z, e2_=kv[1].x, e3_=kv[1].z;              \
        float e4_=kv[2].x, e5_=kv[2].z, e6_=kv[3].x, e7_=kv[3].z;              \
        float o0_=kv[0].y, o1_=kv[0].w, o2_=kv[1].y, o3_=kv[1].w;              \
        float o4_=kv[2].y, o5_=kv[2].w, o6_=kv[3].y, o7_=kv[3].w;              \
        float se_ = ((e0_+e1_)+(e2_+e3_)) + ((e4_+e5_)+(e6_+e7_));             \
        float so_ = ((o0_+o1_)+(o2_+o3_)) + ((o4_+o5_)+(o6_+o7_));             \
        se_ += __shfl_xor_sync(0xffffffffu, se_, 1);                           \
        se_ += __shfl_xor_sync(0xffffffffu, se_, 2);                           \
        so_ += __shfl_xor_sync(0xffffffffu, so_, 1);                           \
        so_ += __shfl_xor_sync(0xffffffffu, so_, 2);                           \
        se_ *= (1.0f / 64.0f);                                                 \
        so_ *= (1.0f / 64.0f);                                                 \
        uint4 ra_, rb_;                                                        \
        ra_.x = h2u(0.5f*e0_+se_, 0.5f*o0_+so_);                               \
        ra_.y = h2u(0.5f*e1_+se_, 0.5f*o1_+so_);                               \
        ra_.z = h2u(0.5f*e2_+se_, 0.5f*o2_+so_);                               \
        ra_.w = h2u(0.5f*e3_+se_, 0.5f*o3_+so_);                               \
        rb_.x = h2u(0.5f*e4_+se_, 0.5f*o4_+so_);                               \
        rb_.y = h2u(0.5f*e5_+se_, 0.5f*o5_+so_);                               \
        rb_.z = h2u(0.5f*e6_+se_, 0.5f*o6_+so_);                               \
        rb_.w = h2u(0.5f*e7_+se_, 0.5f*o7_+so_);                               \
        *(uint4*)&bufp[BS_L + n * 72 + q16]     = ra_;                         \
        *(uint4*)&bufp[BS_L + n * 72 + q16 + 8] = rb_;                         \
        uint4 pe_, po_;                                                        \
        pe_.x = h2u(e0_, e1_); pe_.y = h2u(e2_, e3_);                          \
        pe_.z = h2u(e4_, e5_); pe_.w = h2u(e6_, e7_);                          \
        po_.x = h2u(o0_, o1_); po_.y = h2u(o2_, o3_);                          \
        po_.z = h2u(o4_, o5_); po_.w = h2u(o6_, o7_);                          \
        *(uint4*)&app[n * 40 + q8]        = pe_;                               \
        *(uint4*)&app[5120 + n * 40 + q8] = po_;                               \
    }

#define TRANSFORM(BUF, CP)                                                     \
    {                                                                          \
        __half* bsim = sh + (BUF) * BUFH + BS_L;                               \
        uint32_t offTA = offTA0 + (uint32_t)(CP) * (APC * 2);                  \
        float cacc[4][4];                                                      \
        _Pragma("unroll")                                                      \
        for (int j8_ = 0; j8_ < 4; j8_++)                                      \
            _Pragma("unroll")                                                  \
            for (int r_ = 0; r_ < 4; r_++) cacc[j8_][r_] = 0.0f;               \
        _Pragma("unroll")                                                      \
        for (int s_ = 0; s_ < 2; s_++) {                                       \
            unsigned a_[4];                                                    \
            ldsm_x4(a_, offTA + s_ * 32);                                      \
            _Pragma("unroll")                                                  \
            for (int dt_ = 0; dt_ < 2; dt_++) {                                \
                unsigned bb_[4];                                               \
                ldsm_x4(bb_, offTB + dt_ * (16 * 40 * 2) + s_ * 32);           \
                mma_f16(cacc[dt_ * 2 + 0], a_, bb_[0], bb_[1]);                \
                mma_f16(cacc[dt_ * 2 + 1], a_, bb_[2], bb_[3]);                \
            }                                                                  \
        }                                                                      \
        _Pragma("unroll")                                                      \
        for (int j8_ = 0; j8_ < 4; j8_++) {                                    \
            int col0_ = P + 2 * (j8_ * 8 + 2 * t4);                            \
            int row_  = nblk + g;                                              \
            bsim[(128 + row_) * 72 + col0_]         = __float2half(cacc[j8_][0]); \
            bsim[(128 + row_) * 72 + col0_ + 2]     = __float2half(cacc[j8_][1]); \
            bsim[(128 + row_ + 8) * 72 + col0_]     = __float2half(cacc[j8_][2]); \
            bsim[(128 + row_ + 8) * 72 + col0_ + 2] = __float2half(cacc[j8_][3]); \
        }                                                                      \
    }

    // prologue: buf0 complete, buf1 staged, Apar copies 0 and 1 filled
    LDG_IT(l0);
    __syncthreads();           // taps visible
    STAGE(0, 0);
    LDG_IT(l0 + 1);
    __syncthreads();           // buf0 re + Apar0 visible
    TRANSFORM(0, 0);
    STAGE(1, 1);
    LDG_IT(l0 + 2);
    __syncthreads();           // buf0 complete; buf1 staged; Apar1 visible

    for (int il = 0; il < 32; il++) {
        int bufc = il % 3;
        // all overlapped, single phase:
        if (il + 1 < 32) TRANSFORM((il + 1) % 3, (il + 1) & 1);
        if (il + 2 < 32) {
            STAGE((il + 2) % 3, (il + 2) & 1);
            if (il + 3 < 32) LDG_IT(l0 + il + 3);
        }
        {
            uint32_t bb0 = sb + (uint32_t)(bufc * BUFH) * 2;
#pragma unroll
            for (int s = 0; s < 4; s++) {
                uint32_t so_ = s * 32;
                unsigned a[2][4];
#pragma unroll
                for (int mi = 0; mi < 2; mi++) ldsm_x4(a[mi], bb0 + offA[mi] + so_);
#pragma unroll
                for (int njp = 0; njp < 4; njp++) {
                    unsigned bbv[4];
                    ldsm_x4(bbv, bb0 + offB[njp] + so_);
#pragma unroll
                    for (int mi = 0; mi < 2; mi++) {
                        mma_f16(dacc[mi][2 * njp],     a[mi], bbv[0], bbv[1]);
                        mma_f16(dacc[mi][2 * njp + 1], a[mi], bbv[2], bbv[3]);
                    }
                }
            }
        }
        __syncthreads();
    }

    float* cp = g_Cpart + ((size_t)(kc * BH + bh) * MSEG) * 256;
#pragma unroll
    for (int mi = 0; mi < 2; mi++) {
#pragma unroll
        for (int nj = 0; nj < 8; nj++) {
            int r = m0 + mi * 16 + g;
            int c = j0 + nj * 8 + 2 * t4;
            *(float2*)(cp + (size_t)r * 256 + c)       = make_float2(dacc[mi][nj][0], dacc[mi][nj][1]);
            *(float2*)(cp + (size_t)(r + 8) * 256 + c) = make_float2(dacc[mi][nj][2], dacc[mi][nj][3]);
        }
    }
}

// ---------------------------------------------------------------------------
// Kernel 2: reduce partials, |S|/512, row softmax -> g_Ah (fp16)
// ---------------------------------------------------------------------------
__global__ __launch_bounds__(256) void softmax_k() {
    int bh   = blockIdx.x;
    int m    = blockIdx.y * 8 + (threadIdx.x >> 5);
    int lane = threadIdx.x & 31;

    float t[4];
#pragma unroll
    for (int u = 0; u < 4; u++) {
        int n = lane + u * 32;
        float sre = 0.0f, sim = 0.0f;
#pragma unroll
        for (int p = 0; p < KCH; p++) {
            const float* cp = g_Cpart + (((size_t)p * BH + bh) * MSEG + m) * 256;
            sre += cp[n];
            sim += cp[n + 128];
        }
        t[u] = sqrtf(sre * sre + sim * sim) * (1.0f / 512.0f);
    }
    float mx = fmaxf(fmaxf(t[0], t[1]), fmaxf(t[2], t[3]));
#pragma unroll
    for (int o = 16; o; o >>= 1) mx = fmaxf(mx, __shfl_xor_sync(0xffffffffu, mx, o));
    float e[4], s = 0.0f;
#pragma unroll
    for (int u = 0; u < 4; u++) { e[u] = expf(t[u] - mx); s += e[u]; }
#pragma unroll
    for (int o = 16; o; o >>= 1) s += __shfl_xor_sync(0xffffffffu, s, o);
    float inv = 1.0f / s;
    __half* arow = g_Ah + ((size_t)bh * MSEG + m) * MSEG;
#pragma unroll
    for (int u = 0; u < 4; u++) arow[lane + u * 32] = __float2half(e[u] * inv);
}

// ---------------------------------------------------------------------------
// Kernel 3: out = A @ v, FP16 mma. A resident, 8 l per CTA, v double-buffered,
// single sync per l. grid (bh*8), block 256.  (unchanged)
// ---------------------------------------------------------------------------
__global__ __launch_bounds__(256, 2) void v_gemm_h3(const float* __restrict__ v,
                                                    float* __restrict__ out) {
    extern __shared__ char dynsm[];
    __half (*As)[136]  = (__half(*)[136])dynsm;
    __half2 (*vsp)[72] = (__half2(*)[72])(dynsm + 128 * 136 * 2);

    int bx = blockIdx.x;
    int lg = bx & 7;
    int bh = bx >> 3;
    int b  = bh >> 4, h = bh & 15;
    int tid  = threadIdx.x;
    int lane = tid & 31;
    int w    = tid >> 5;
    int g = lane >> 2, t = lane & 3;
    int m0 = (w >> 1) * 32;
    int d0 = (w & 1) * 32;

    const __half* Abase = g_Ah + (size_t)bh * MSEG * MSEG;
    const float* vbh    = v + (size_t)b * BSTRIDE + h * DDIM;
    float* obh          = out + (size_t)b * BSTRIDE + h * DDIM;

    int kpV = tid >> 4;
    int d4V = tid & 15;

    float4 pv[8];
    {
        const float* vb = vbh + (size_t)(lg * LPB) * ROWSTRIDE;
#pragma unroll
        for (int i = 0; i < 4; i++) {
            int kp = kpV + 16 * i;
            pv[2 * i]     = *(const float4*)(vb + (size_t)(2 * kp) * SEGSTRIDE + d4V * 4);
            pv[2 * i + 1] = *(const float4*)(vb + (size_t)(2 * kp + 1) * SEGSTRIDE + d4V * 4);
        }
    }

#pragma unroll
    for (int i = 0; i < 8; i++) {
        int idx = tid + i * 256;
        int m = idx >> 4, c = idx & 15;
        uint4 u = *(const uint4*)(Abase + (size_t)m * MSEG + c * 8);
        *(uint4*)&As[m][c * 8] = u;
    }

    for (int il = 0; il < LPB; il++) {
        int l   = lg * LPB + il;
        int buf = (il & 1) * 64;
#pragma unroll
        for (int i = 0; i < 4; i++) {
            int kp = kpV + 16 * i;
            uint4 u;
            u.x = h2u(pv[2 * i].x, pv[2 * i + 1].x);
            u.y = h2u(pv[2 * i].y, pv[2 * i + 1].y);
            u.z = h2u(pv[2 * i].z, pv[2 * i + 1].z);
            u.w = h2u(pv[2 * i].w, pv[2 * i + 1].w);
            *(uint4*)&vsp[buf + kp][d4V * 4] = u;
        }
        if (il + 1 < LPB) {
            const float* vb = vbh + (size_t)(l + 1) * ROWSTRIDE;
#pragma unroll
            for (int i = 0; i < 4; i++) {
                int kp = kpV + 16 * i;
                pv[2 * i]     = *(const float4*)(vb + (size_t)(2 * kp) * SEGSTRIDE + d4V * 4);
                pv[2 * i + 1] = *(const float4*)(vb + (size_t)(2 * kp + 1) * SEGSTRIDE + d4V * 4);
            }
        }
        __syncthreads();

        float dacc[2][4][4];
#pragma unroll
        for (int mi = 0; mi < 2; mi++)
#pragma unroll
            for (int dj = 0; dj < 4; dj++)
#pragma unroll
                for (int r = 0; r < 4; r++) dacc[mi][dj][r] = 0.0f;

#pragma unroll
        for (int s = 0; s < 8; s++) {
            int kb16 = s * 16;
            unsigned bb[4][2];
#pragma unroll
            for (int dj = 0; dj < 4; dj++) {
                int c = d0 + dj * 8 + g;
                bb[dj][0] = *(const unsigned*)&vsp[buf + s * 8 + t][c];
                bb[dj][1] = *(const unsigned*)&vsp[buf + s * 8 + t + 4][c];
            }
#pragma unroll
            for (int mi = 0; mi < 2; mi++) {
                int r = m0 + mi * 16 + g;
                unsigned a[4];
                a[0] = *(const unsigned*)&As[r][kb16 + 2 * t];
                a[1] = *(const unsigned*)&As[r + 8][kb16 + 2 * t];
                a[2] = *(const unsigned*)&As[r][kb16 + 2 * t + 8];
                a[3] = *(const unsigned*)&As[r + 8][kb16 + 2 * t + 8];
#pragma unroll
                for (int dj = 0; dj < 4; dj++) mma_f16(dacc[mi][dj], a, bb[dj][0], bb[dj][1]);
            }
        }

        float* obase = obh + (size_t)l * ROWSTRIDE;
#pragma unroll
        for (int mi = 0; mi < 2; mi++) {
#pragma unroll
            for (int dj = 0; dj < 4; dj++) {
                int r = m0 + mi * 16 + g;
                int c = d0 + dj * 8 + 2 * t;
                *(float2*)(obase + (size_t)r * SEGSTRIDE + c)       = make_float2(dacc[mi][dj][0], dacc[mi][dj][1]);
                *(float2*)(obase + (size_t)(r + 8) * SEGSTRIDE + c) = make_float2(dacc[mi][dj][2], dacc[mi][dj][3]);
            }
        }
    }
}

#define VG_SMEM (128 * 136 * 2 + 2 * 64 * 72 * 4)

// ---------------------------------------------------------------------------
extern "C" void kernel_launch(void* const* d_in, const int* in_sizes, int n_in,
                              void* d_out, int out_size) {
    const float* q = (const float*)d_in[0];
    const float* k = (const float*)d_in[1];
    const float* v = (const float*)d_in[2];
    float* out = (float*)d_out;

    cudaFuncSetAttribute(scores_fused4, cudaFuncAttributeMaxDynamicSharedMemorySize, FS_SMEM);
    cudaFuncSetAttribute(v_gemm_h3, cudaFuncAttributeMaxDynamicSharedMemorySize, VG_SMEM);

    scores_fused4<<<dim3(KCH, BH), 512, FS_SMEM>>>(q, k);
    softmax_k<<<dim3(BH, 16), 256>>>();
    v_gemm_h3<<<BH * LPB, 256, VG_SMEM>>>(v, out);
}

// round 15
// speedup vs baseline: 1.1825x; 1.1825x over previous
#include <cuda_runtime.h>
#include <cuda_fp16.h>
#include <math.h>
#include <stdint.h>

// FourierAttention R15: scores reverted to R13's proven 2-phase double-buffered
// schedule (R14's 1-barrier rotation spilled registers and regressed).
// v_gemm: LPB 8->16 so all 256 CTAs are resident in ONE wave (no wave quant).
// B=4, L=8192, H=16, D=64, Ls=64, M=128.

#define BDIM 4
#define LDIM 8192
#define HDIM 16
#define DDIM 64
#define LSEG 64
#define MSEG 128
#define BH   64
#define KDIM 4096
#define KCH  2
#define LPB  16
#define ROWSTRIDE 1024
#define SEGSTRIDE 65536
#define BSTRIDE (LDIM*ROWSTRIDE)

// Scratch (device globals: allocation-free, graph-capture safe)
__device__ float g_Cpart[(size_t)KCH * BH * MSEG * 256]; // score partials
__device__ __half g_Ah[(size_t)BH * MSEG * MSEG];        // softmax result (fp16)

__device__ __forceinline__ void mma_f16(float* d, const unsigned* a,
                                        unsigned b0, unsigned b1) {
    asm volatile(
        "mma.sync.aligned.m16n8k16.row.col.f32.f16.f16.f32 "
        "{%0,%1,%2,%3},{%4,%5,%6,%7},{%8,%9},{%0,%1,%2,%3};"
        : "+f"(d[0]), "+f"(d[1]), "+f"(d[2]), "+f"(d[3])
        : "r"(a[0]), "r"(a[1]), "r"(a[2]), "r"(a[3]), "r"(b0), "r"(b1));
}

__device__ __forceinline__ unsigned h2u(float a, float b) {
    __half2 h = __floats2half2_rn(a, b);
    return *(unsigned*)&h;
}

__device__ __forceinline__ uint32_t smem_u32(const void* p) {
    uint32_t a;
    asm("{ .reg .u64 t; cvta.to.shared.u64 t, %1; cvt.u32.u64 %0, t; }" : "=r"(a) : "l"(p));
    return a;
}

__device__ __forceinline__ void ldsm_x4(unsigned* r, uint32_t addr) {
    asm volatile("ldmatrix.sync.aligned.m8n8.x4.shared.b16 {%0,%1,%2,%3}, [%4];"
        : "=r"(r[0]), "=r"(r[1]), "=r"(r[2]), "=r"(r[3]) : "r"(addr));
}

// smem layout (halves): 2 buffers of [As 128x72 | Bs 256x72], Apar, taps
#define AS_L 0
#define BS_L (128 * 72)                 // buffer-local
#define BUFH ((128 + 256) * 72)         // 27648 halves per buffer
#define AP_H (2 * BUFH)                 // 55296: Apar[2][128][40] (single copy)
#define TP_H (AP_H + 2 * 128 * 40)      // 65536: taps[2][32][40]
#define TOT_H (TP_H + 2 * 32 * 40)      // 68096 halves
#define FS_SMEM (TOT_H * 2)             // 136192 bytes

__global__ __launch_bounds__(512, 1) void scores_fused3(const float* __restrict__ q,
                                                        const float* __restrict__ kin) {
    extern __shared__ __half sh[];

    int kc = blockIdx.x;
    int bh = blockIdx.y;
    int b  = bh >> 4, h = bh & 15;
    int tid  = threadIdx.x;
    int lane = tid & 31;
    int w    = tid >> 5;
    int g = lane >> 2, t4 = lane & 3;
    int m0 = (w >> 2) * 32;
    int j0 = (w & 3) * 64;

    // taps[which][dd][t]
#pragma unroll
    for (int i = tid; i < 2048; i += 512) {
        int which = i >> 10, dd = (i >> 5) & 31, tt = i & 31;
        int delta = which ? (2 * dd + 1 - 2 * tt) : (2 * dd - 2 * tt - 1);
        float x = (float)delta * (1.0f / 64.0f);
        sh[TP_H + which * 1280 + dd * 40 + tt] =
            __float2half(-(cospif(x) / sinpif(x)) * (1.0f / 64.0f));
    }

    float dacc[2][8][4];
#pragma unroll
    for (int mi = 0; mi < 2; mi++)
#pragma unroll
        for (int nj = 0; nj < 8; nj++)
#pragma unroll
            for (int r = 0; r < 4; r++) dacc[mi][nj][r] = 0.0f;

    const float* qb = q   + (size_t)b * BSTRIDE + h * DDIM;
    const float* kb = kin + (size_t)b * BSTRIDE + h * DDIM;

    // staging indices (4 threads per row)
    int n   = tid >> 2;
    int q16 = (tid & 3) * 16;
    int q8  = (tid & 3) * 8;

    uint32_t sb = smem_u32(sh);
    // main-MMA ldsm byte offsets (buffer-local)
    uint32_t offA[2], offB[4];
#pragma unroll
    for (int mi = 0; mi < 2; mi++) {
        int row = m0 + mi * 16 + (lane & 7) + ((lane >> 3) & 1) * 8;
        int col = ((lane >> 4) & 1) * 8;
        offA[mi] = (uint32_t)(AS_L + row * 72 + col) * 2;
    }
#pragma unroll
    for (int njp = 0; njp < 4; njp++) {
        int row = j0 + njp * 16 + (lane & 7) + ((lane >> 4) & 1) * 8;
        int col = ((lane >> 3) & 1) * 8;
        offB[njp] = (uint32_t)(BS_L + row * 72 + col) * 2;
    }
    // transform: warp w handles parity P over 16 n-rows
    int P    = w & 1;
    int nblk = (w >> 1) * 16;
    uint32_t offTA, offTB;
    {
        int arow = nblk + (lane & 7) + ((lane >> 3) & 1) * 8;
        int acol = ((lane >> 4) & 1) * 8;
        offTA = sb + (uint32_t)(AP_H + (1 - P) * 5120 + arow * 40 + acol) * 2;
        int brow = (lane & 7) + ((lane >> 4) & 1) * 8;
        int bcol = ((lane >> 3) & 1) * 8;
        offTB = sb + (uint32_t)(TP_H + P * 1280 + brow * 40 + bcol) * 2;
    }

    int l0 = kc * 32;
    float4 qv[4], kv[4];

#define LDG_IT(LIDX)                                                           \
    {                                                                          \
        const float* sq_ = qb + (size_t)(n * LSEG + (LIDX)) * ROWSTRIDE + q16; \
        const float* sk_ = kb + (size_t)(n * LSEG + (LIDX)) * ROWSTRIDE + q16; \
        _Pragma("unroll")                                                      \
        for (int i_ = 0; i_ < 4; i_++) {                                       \
            qv[i_] = *(const float4*)(sq_ + 4 * i_);                           \
            kv[i_] = *(const float4*)(sk_ + 4 * i_);                           \
        }                                                                      \
    }

#define STAGE(BUF)                                                             \
    {                                                                          \
        __half* bufp = sh + (BUF) * BUFH;                                      \
        uint4 ua_, ub_;                                                        \
        ua_.x = h2u(qv[0].x, qv[0].y); ua_.y = h2u(qv[0].z, qv[0].w);          \
        ua_.z = h2u(qv[1].x, qv[1].y); ua_.w = h2u(qv[1].z, qv[1].w);          \
        ub_.x = h2u(qv[2].x, qv[2].y); ub_.y = h2u(qv[2].z, qv[2].w);          \
        ub_.z = h2u(qv[3].x, qv[3].y); ub_.w = h2u(qv[3].z, qv[3].w);          \
        *(uint4*)&bufp[AS_L + n * 72 + q16]     = ua_;                         \
        *(uint4*)&bufp[AS_L + n * 72 + q16 + 8] = ub_;                         \
        float e0_=kv[0].x, e1_=kv[0].z, e2_=kv[1].x, e3_=kv[1].z;              \
        float e4_=kv[2].x, e5_=kv[2].z, e6_=kv[3].x, e7_=kv[3].z;              \
        float o0_=kv[0].y, o1_=kv[0].w, o2_=kv[1].y, o3_=kv[1].w;              \
        float o4_=kv[2].y, o5_=kv[2].w, o6_=kv[3].y, o7_=kv[3].w;              \
        float se_ = ((e0_+e1_)+(e2_+e3_)) + ((e4_+e5_)+(e6_+e7_));             \
        float so_ = ((o0_+o1_)+(o2_+o3_)) + ((o4_+o5_)+(o6_+o7_));             \
        se_ += __shfl_xor_sync(0xffffffffu, se_, 1);                           \
        se_ += __shfl_xor_sync(0xffffffffu, se_, 2);                           \
        so_ += __shfl_xor_sync(0xffffffffu, so_, 1);                           \
        so_ += __shfl_xor_sync(0xffffffffu, so_, 2);                           \
        se_ *= (1.0f / 64.0f);                                                 \
        so_ *= (1.0f / 64.0f);                                                 \
        uint4 ra_, rb_;                                                        \
        ra_.x = h2u(0.5f*e0_+se_, 0.5f*o0_+so_);                               \
        ra_.y = h2u(0.5f*e1_+se_, 0.5f*o1_+so_);                               \
        ra_.z = h2u(0.5f*e2_+se_, 0.5f*o2_+so_);                               \
        ra_.w = h2u(0.5f*e3_+se_, 0.5f*o3_+so_);                               \
        rb_.x = h2u(0.5f*e4_+se_, 0.5f*o4_+so_);                               \
        rb_.y = h2u(0.5f*e5_+se_, 0.5f*o5_+so_);                               \
        rb_.z = h2u(0.5f*e6_+se_, 0.5f*o6_+so_);                               \
        rb_.w = h2u(0.5f*e7_+se_, 0.5f*o7_+so_);                               \
        *(uint4*)&bufp[BS_L + n * 72 + q16]     = ra_;                         \
        *(uint4*)&bufp[BS_L + n * 72 + q16 + 8] = rb_;                         \
        uint4 pe_, po_;                                                        \
        pe_.x = h2u(e0_, e1_); pe_.y = h2u(e2_, e3_);                          \
        pe_.z = h2u(e4_, e5_); pe_.w = h2u(e6_, e7_);                          \
        po_.x = h2u(o0_, o1_); po_.y = h2u(o2_, o3_);                          \
        po_.z = h2u(o4_, o5_); po_.w = h2u(o6_, o7_);                          \
        *(uint4*)&sh[AP_H + n * 40 + q8]        = pe_;                         \
        *(uint4*)&sh[AP_H + 5120 + n * 40 + q8] = po_;                         \
    }

#define TRANSFORM(BUF)                                                         \
    {                                                                          \
        __half* bsim = sh + (BUF) * BUFH + BS_L;                               \
        float cacc[4][4];                                                      \
        _Pragma("unroll")                                                      \
        for (int j8_ = 0; j8_ < 4; j8_++)                                      \
            _Pragma("unroll")                                                  \
            for (int r_ = 0; r_ < 4; r_++) cacc[j8_][r_] = 0.0f;               \
        _Pragma("unroll")                                                      \
        for (int s_ = 0; s_ < 2; s_++) {                                       \
            unsigned a_[4];                                                    \
            ldsm_x4(a_, offTA + s_ * 32);                                      \
            _Pragma("unroll")                                                  \
            for (int dt_ = 0; dt_ < 2; dt_++) {                                \
                unsigned bb_[4];                                               \
                ldsm_x4(bb_, offTB + dt_ * (16 * 40 * 2) + s_ * 32);           \
                mma_f16(cacc[dt_ * 2 + 0], a_, bb_[0], bb_[1]);                \
                mma_f16(cacc[dt_ * 2 + 1], a_, bb_[2], bb_[3]);                \
            }                                                                  \
        }                                                                      \
        _Pragma("unroll")                                                      \
        for (int j8_ = 0; j8_ < 4; j8_++) {                                    \
            int col0_ = P + 2 * (j8_ * 8 + 2 * t4);                            \
            int row_  = nblk + g;                                              \
            bsim[(128 + row_) * 72 + col0_]         = __float2half(cacc[j8_][0]); \
            bsim[(128 + row_) * 72 + col0_ + 2]     = __float2half(cacc[j8_][1]); \
            bsim[(128 + row_ + 8) * 72 + col0_]     = __float2half(cacc[j8_][2]); \
            bsim[(128 + row_ + 8) * 72 + col0_ + 2] = __float2half(cacc[j8_][3]); \
        }                                                                      \
    }

    // prologue
    LDG_IT(l0);
    __syncthreads();           // taps visible
    STAGE(0);                  // stage l0 into buf0
    LDG_IT(l0 + 1);
    __syncthreads();           // Apar(l0) visible
    TRANSFORM(0);
    __syncthreads();           // Bs-im(buf0) visible

    for (int il = 0; il < 32; il++) {
        int buf = il & 1;
        // phase 1: stage next tile (other buffer) + prefetch, then main MMA
        if (il + 1 < 32) {
            STAGE(buf ^ 1);                 // data l0+il+1
            if (il + 2 < 32) LDG_IT(l0 + il + 2);
        }
        {
            uint32_t bb0 = sb + (uint32_t)(buf * BUFH) * 2;
#pragma unroll
            for (int s = 0; s < 4; s++) {
                uint32_t so_ = s * 32;
                unsigned a[2][4];
#pragma unroll
                for (int mi = 0; mi < 2; mi++) ldsm_x4(a[mi], bb0 + offA[mi] + so_);
#pragma unroll
                for (int njp = 0; njp < 4; njp++) {
                    unsigned bbv[4];
                    ldsm_x4(bbv, bb0 + offB[njp] + so_);
#pragma unroll
                    for (int mi = 0; mi < 2; mi++) {
                        mma_f16(dacc[mi][2 * njp],     a[mi], bbv[0], bbv[1]);
                        mma_f16(dacc[mi][2 * njp + 1], a[mi], bbv[2], bbv[3]);
                    }
                }
            }
        }
        __syncthreads();   // Apar visible; buf^1 prev readers released
        // phase 2: transform im-rows of next buffer
        if (il + 1 < 32) {
            TRANSFORM(buf ^ 1);
            __syncthreads();   // Bs-im(buf^1) visible before its main MMA
        }
    }

    float* cp = g_Cpart + ((size_t)(kc * BH + bh) * MSEG) * 256;
#pragma unroll
    for (int mi = 0; mi < 2; mi++) {
#pragma unroll
        for (int nj = 0; nj < 8; nj++) {
            int r = m0 + mi * 16 + g;
            int c = j0 + nj * 8 + 2 * t4;
            *(float2*)(cp + (size_t)r * 256 + c)       = make_float2(dacc[mi][nj][0], dacc[mi][nj][1]);
            *(float2*)(cp + (size_t)(r + 8) * 256 + c) = make_float2(dacc[mi][nj][2], dacc[mi][nj][3]);
        }
    }
}

// ---------------------------------------------------------------------------
// Kernel 2: reduce partials, |S|/512, row softmax -> g_Ah (fp16)
// ---------------------------------------------------------------------------
__global__ __launch_bounds__(256) void softmax_k() {
    int bh   = blockIdx.x;
    int m    = blockIdx.y * 8 + (threadIdx.x >> 5);
    int lane = threadIdx.x & 31;

    float t[4];
#pragma unroll
    for (int u = 0; u < 4; u++) {
        int n = lane + u * 32;
        float sre = 0.0f, sim = 0.0f;
#pragma unroll
        for (int p = 0; p < KCH; p++) {
            const float* cp = g_Cpart + (((size_t)p * BH + bh) * MSEG + m) * 256;
            sre += cp[n];
            sim += cp[n + 128];
        }
        t[u] = sqrtf(sre * sre + sim * sim) * (1.0f / 512.0f);
    }
    float mx = fmaxf(fmaxf(t[0], t[1]), fmaxf(t[2], t[3]));
#pragma unroll
    for (int o = 16; o; o >>= 1) mx = fmaxf(mx, __shfl_xor_sync(0xffffffffu, mx, o));
    float e[4], s = 0.0f;
#pragma unroll
    for (int u = 0; u < 4; u++) { e[u] = expf(t[u] - mx); s += e[u]; }
#pragma unroll
    for (int o = 16; o; o >>= 1) s += __shfl_xor_sync(0xffffffffu, s, o);
    float inv = 1.0f / s;
    __half* arow = g_Ah + ((size_t)bh * MSEG + m) * MSEG;
#pragma unroll
    for (int u = 0; u < 4; u++) arow[lane + u * 32] = __float2half(e[u] * inv);
}

// ---------------------------------------------------------------------------
// Kernel 3: out = A @ v, FP16 mma. A resident, LPB=16 l per CTA (grid 256 =
// one resident wave at 2 CTA/SM), v double-buffered, single sync per l.
// ---------------------------------------------------------------------------
__global__ __launch_bounds__(256, 2) void v_gemm_h3(const float* __restrict__ v,
                                                    float* __restrict__ out) {
    extern __shared__ char dynsm[];
    __half (*As)[136]  = (__half(*)[136])dynsm;
    __half2 (*vsp)[72] = (__half2(*)[72])(dynsm + 128 * 136 * 2);

    int bx = blockIdx.x;
    int lg = bx & 3;                     // 4 l-groups of 16
    int bh = bx >> 2;
    int b  = bh >> 4, h = bh & 15;
    int tid  = threadIdx.x;
    int lane = tid & 31;
    int w    = tid >> 5;
    int g = lane >> 2, t = lane & 3;
    int m0 = (w >> 1) * 32;
    int d0 = (w & 1) * 32;

    const __half* Abase = g_Ah + (size_t)bh * MSEG * MSEG;
    const float* vbh    = v + (size_t)b * BSTRIDE + h * DDIM;
    float* obh          = out + (size_t)b * BSTRIDE + h * DDIM;

    int kpV = tid >> 4;
    int d4V = tid & 15;

    float4 pv[8];
    {
        const float* vb = vbh + (size_t)(lg * LPB) * ROWSTRIDE;
#pragma unroll
        for (int i = 0; i < 4; i++) {
            int kp = kpV + 16 * i;
            pv[2 * i]     = *(const float4*)(vb + (size_t)(2 * kp) * SEGSTRIDE + d4V * 4);
            pv[2 * i + 1] = *(const float4*)(vb + (size_t)(2 * kp + 1) * SEGSTRIDE + d4V * 4);
        }
    }

#pragma unroll
    for (int i = 0; i < 8; i++) {
        int idx = tid + i * 256;
        int m = idx >> 4, c = idx & 15;
        uint4 u = *(const uint4*)(Abase + (size_t)m * MSEG + c * 8);
        *(uint4*)&As[m][c * 8] = u;
    }

    for (int il = 0; il < LPB; il++) {
        int l   = lg * LPB + il;
        int buf = (il & 1) * 64;
#pragma unroll
        for (int i = 0; i < 4; i++) {
            int kp = kpV + 16 * i;
            uint4 u;
            u.x = h2u(pv[2 * i].x, pv[2 * i + 1].x);
            u.y = h2u(pv[2 * i].y, pv[2 * i + 1].y);
            u.z = h2u(pv[2 * i].z, pv[2 * i + 1].z);
            u.w = h2u(pv[2 * i].w, pv[2 * i + 1].w);
            *(uint4*)&vsp[buf + kp][d4V * 4] = u;
        }
        if (il + 1 < LPB) {
            const float* vb = vbh + (size_t)(l + 1) * ROWSTRIDE;
#pragma unroll
            for (int i = 0; i < 4; i++) {
                int kp = kpV + 16 * i;
                pv[2 * i]     = *(const float4*)(vb + (size_t)(2 * kp) * SEGSTRIDE + d4V * 4);
                pv[2 * i + 1] = *(const float4*)(vb + (size_t)(2 * kp + 1) * SEGSTRIDE + d4V * 4);
            }
        }
        __syncthreads();

        float dacc[2][4][4];
#pragma unroll
        for (int mi = 0; mi < 2; mi++)
#pragma unroll
            for (int dj = 0; dj < 4; dj++)
#pragma unroll
                for (int r = 0; r < 4; r++) dacc[mi][dj][r] = 0.0f;

#pragma unroll
        for (int s = 0; s < 8; s++) {
            int kb16 = s * 16;
            unsigned bb[4][2];
#pragma unroll
            for (int dj = 0; dj < 4; dj++) {
                int c = d0 + dj * 8 + g;
                bb[dj][0] = *(const unsigned*)&vsp[buf + s * 8 + t][c];
                bb[dj][1] = *(const unsigned*)&vsp[buf + s * 8 + t + 4][c];
            }
#pragma unroll
            for (int mi = 0; mi < 2; mi++) {
                int r = m0 + mi * 16 + g;
                unsigned a[4];
                a[0] = *(const unsigned*)&As[r][kb16 + 2 * t];
                a[1] = *(const unsigned*)&As[r + 8][kb16 + 2 * t];
                a[2] = *(const unsigned*)&As[r][kb16 + 2 * t + 8];
                a[3] = *(const unsigned*)&As[r + 8][kb16 + 2 * t + 8];
#pragma unroll
                for (int dj = 0; dj < 4; dj++) mma_f16(dacc[mi][dj], a, bb[dj][0], bb[dj][1]);
            }
        }

        float* obase = obh + (size_t)l * ROWSTRIDE;
#pragma unroll
        for (int mi = 0; mi < 2; mi++) {
#pragma unroll
            for (int dj = 0; dj < 4; dj++) {
                int r = m0 + mi * 16 + g;
                int c = d0 + dj * 8 + 2 * t;
                *(float2*)(obase + (size_t)r * SEGSTRIDE + c)       = make_float2(dacc[mi][dj][0], dacc[mi][dj][1]);
                *(float2*)(obase + (size_t)(r + 8) * SEGSTRIDE + c) = make_float2(dacc[mi][dj][2], dacc[mi][dj][3]);
            }
        }
    }
}

#define VG_SMEM (128 * 136 * 2 + 2 * 64 * 72 * 4)

// ---------------------------------------------------------------------------
extern "C" void kernel_launch(void* const* d_in, const int* in_sizes, int n_in,
                              void* d_out, int out_size) {
    const float* q = (const float*)d_in[0];
    const float* k = (const float*)d_in[1];
    const float* v = (const float*)d_in[2];
    float* out = (float*)d_out;

    cudaFuncSetAttribute(scores_fused3, cudaFuncAttributeMaxDynamicSharedMemorySize, FS_SMEM);
    cudaFuncSetAttribute(v_gemm_h3, cudaFuncAttributeMaxDynamicSharedMemorySize, VG_SMEM);

    scores_fused3<<<dim3(KCH, BH), 512, FS_SMEM>>>(q, k);
    softmax_k<<<dim3(BH, 16), 256>>>();
    v_gemm_h3<<<BH * (LSEG / LPB), 256, VG_SMEM>>>(v, out);
}